// round 10
// baseline (speedup 1.0000x reference)
#include <cuda_runtime.h>
#include <cuda_bf16.h>
#include <cuda_fp16.h>

typedef unsigned int       u32;
typedef unsigned long long u64;

// Problem constants
constexpr int Bn  = 2;
constexpr int Tn  = 2048;
constexpr int Cn  = 2048;
constexpr int Hn  = 16;
constexpr int HDn = 128;
constexpr float SCALE = 0.088388347648318447f;   // 1/sqrt(128)
constexpr float EPSv  = 1e-6f;

// ---------------------------------------------------------------------------
// Device-global scratch
// ---------------------------------------------------------------------------
__device__ __nv_bfloat16 g_Qhi[(size_t)Bn * Hn * Tn * HDn];  // [B,H,T,hd]
__device__ __nv_bfloat16 g_Qlo[(size_t)Bn * Hn * Tn * HDn];
__device__ __nv_bfloat16 g_Khi[(size_t)Bn * Hn * Tn * HDn];
__device__ __nv_bfloat16 g_Klo[(size_t)Bn * Hn * Tn * HDn];
__device__ __half        g_Vh [(size_t)Bn * Hn * Tn * HDn];

__device__ __half g_Xhi[(size_t)Bn * Tn * Cn];
__device__ __half g_Xlo[(size_t)Bn * Tn * Cn];
__device__ __half g_Wh[4][(size_t)Cn * Cn];
__device__ __half g_Ahi[(size_t)Bn * Tn * Cn];      // attn out hi/lo fp16
__device__ __half g_Alo[(size_t)Bn * Tn * Cn];

// ---------------------------------------------------------------------------
// PTX helpers
// ---------------------------------------------------------------------------
__device__ __forceinline__ u32 smem_to_u32(const void* p) {
    u32 a;
    asm("{ .reg .u64 t; cvta.to.shared.u64 t, %1; cvt.u32.u64 %0, t; }"
        : "=r"(a) : "l"(p));
    return a;
}

__device__ __forceinline__ void cp16(u32 saddr, const void* g) {
    asm volatile("cp.async.cg.shared.global [%0], [%1], 16;"
                 :: "r"(saddr), "l"(g) : "memory");
}
#define CP_COMMIT() asm volatile("cp.async.commit_group;" ::: "memory")
#define CP_WAIT(n)  asm volatile("cp.async.wait_group %0;" :: "n"(n) : "memory")

__device__ __forceinline__ void ldsm_x4(u32& r0, u32& r1, u32& r2, u32& r3, u32 addr) {
    asm volatile("ldmatrix.sync.aligned.m8n8.x4.shared.b16 {%0,%1,%2,%3}, [%4];"
                 : "=r"(r0), "=r"(r1), "=r"(r2), "=r"(r3) : "r"(addr));
}
__device__ __forceinline__ void ldsm_x4_t(u32& r0, u32& r1, u32& r2, u32& r3, u32 addr) {
    asm volatile("ldmatrix.sync.aligned.m8n8.x4.trans.shared.b16 {%0,%1,%2,%3}, [%4];"
                 : "=r"(r0), "=r"(r1), "=r"(r2), "=r"(r3) : "r"(addr));
}

__device__ __forceinline__ void mma16816(float* d, const u32* a, const u32* b) {
    asm volatile(
        "mma.sync.aligned.m16n8k16.row.col.f32.bf16.bf16.f32 "
        "{%0,%1,%2,%3}, {%4,%5,%6,%7}, {%8,%9}, {%0,%1,%2,%3};"
        : "+f"(d[0]), "+f"(d[1]), "+f"(d[2]), "+f"(d[3])
        : "r"(a[0]), "r"(a[1]), "r"(a[2]), "r"(a[3]), "r"(b[0]), "r"(b[1]));
}
__device__ __forceinline__ void mma16816h(float* d, const u32* a, const u32* b) {
    asm volatile(
        "mma.sync.aligned.m16n8k16.row.col.f32.f16.f16.f32 "
        "{%0,%1,%2,%3}, {%4,%5,%6,%7}, {%8,%9}, {%0,%1,%2,%3};"
        : "+f"(d[0]), "+f"(d[1]), "+f"(d[2]), "+f"(d[3])
        : "r"(a[0]), "r"(a[1]), "r"(a[2]), "r"(a[3]), "r"(b[0]), "r"(b[1]));
}

// pack {lo, hi} floats (lo -> bits[15:0])
__device__ __forceinline__ u32 pack_bf16x2(float lo, float hi) {
    u32 r;
    asm("cvt.rn.bf16x2.f32 %0, %1, %2;" : "=r"(r) : "f"(hi), "f"(lo));
    return r;
}
__device__ __forceinline__ u32 pack_f16x2(float lo, float hi) {
    u32 r;
    asm("cvt.rn.f16x2.f32 %0, %1, %2;" : "=r"(r) : "f"(hi), "f"(lo));
    return r;
}

// ---------------------------------------------------------------------------
// fp32 -> fp16 hi/lo split of X
// ---------------------------------------------------------------------------
__global__ void split_x_kernel(const float* __restrict__ in, int n)
{
    int i = (blockIdx.x * blockDim.x + threadIdx.x) * 4;
    if (i >= n) return;
    float4 v = *(const float4*)(in + i);
    __half h0 = __float2half(v.x), h1 = __float2half(v.y);
    __half h2 = __float2half(v.z), h3 = __float2half(v.w);
    __half l0 = __float2half(v.x - __half2float(h0));
    __half l1 = __float2half(v.y - __half2float(h1));
    __half l2 = __float2half(v.z - __half2float(h2));
    __half l3 = __float2half(v.w - __half2float(h3));
    __half2* hp = (__half2*)(g_Xhi + i);
    __half2* lp = (__half2*)(g_Xlo + i);
    hp[0] = __halves2half2(h0, h1); hp[1] = __halves2half2(h2, h3);
    lp[0] = __halves2half2(l0, l1); lp[1] = __halves2half2(l2, l3);
}

// fp32 -> fp16 single conversion of a weight matrix
__global__ void conv_w_kernel(const float* __restrict__ in, int which, int n)
{
    int i = (blockIdx.x * blockDim.x + threadIdx.x) * 4;
    if (i >= n) return;
    float4 v = *(const float4*)(in + i);
    __half2* p = (__half2*)(g_Wh[which] + i);
    p[0] = __halves2half2(__float2half(v.x), __float2half(v.y));
    p[1] = __halves2half2(__float2half(v.z), __float2half(v.w));
}

// ---------------------------------------------------------------------------
// HMMA fp16 2-pass GEMM:  out[m,n] = sum_k (Ahi+Alo)[m,k] * W[n,k]
// CTA tile 128x128, 128 threads (4 warps, 2x2), warp tile 64x64, BK=32,
// double-buffered cp.async, 2 CTAs/SM.
// Each thread loads one full 64B row segment (4 cp16) per matrix tile.
// isOut==0: A=X, B=W[z]; out -> Q/K bf16 hi/lo, V fp16, [B,H,T,hd]
// isOut==1: A=attn out (fp16 hi/lo), B=Wo; out -> fp32 OutParam
// ---------------------------------------------------------------------------
constexpr int GBK     = 32;
constexpr int LDS_H   = 40;                       // halves per row (32+8)
constexpr int TILE_B  = 128 * LDS_H * 2;          // 10240
constexpr int STAGE_B = 3 * TILE_B;               // 30720
constexpr int GEMM_SMEM = 2 * STAGE_B;            // 61440
constexpr int NCHUNK  = Cn / GBK;                 // 64

__global__ __launch_bounds__(128, 2)
void gemm_f16(int isOut, float* __restrict__ OutParam)
{
    extern __shared__ char smem[];
    const u32 sbase = smem_to_u32(smem);
    const int tid  = threadIdx.x;
    const int lane = tid & 31;
    const int warp = tid >> 5;      // 0..3
    const int wr   = warp >> 1;     // 0..1 : 64-row group
    const int wc   = warp & 1;      // 0..1 : 64-col group

    const int mat = isOut ? 3 : blockIdx.z;
    const __half* __restrict__ Ahi = isOut ? g_Ahi : g_Xhi;
    const __half* __restrict__ Alo = isOut ? g_Alo : g_Xlo;
    const __half* __restrict__ Bm  = g_Wh[mat];

    const int mBase = blockIdx.y * 128;
    const int nBase = blockIdx.x * 128;

    float acc[4][8][4];
#pragma unroll
    for (int i = 0; i < 4; i++)
#pragma unroll
        for (int j = 0; j < 8; j++)
#pragma unroll
            for (int r = 0; r < 4; r++) acc[i][j][r] = 0.f;

    // loaders: each thread owns one row (tid); 4 cp16 (=32 halves) per tile
    auto load_chunk = [&](int kc, int s) {
        const u32 sb = sbase + s * STAGE_B;
        const int k0 = kc * GBK;
        const u32 so = (u32)(tid * LDS_H) * 2;
        {
            const __half* g = Ahi + (size_t)(mBase + tid) * Cn + k0;
            cp16(sb + so,      g);
            cp16(sb + so + 16, g + 8);
            cp16(sb + so + 32, g + 16);
            cp16(sb + so + 48, g + 24);
        }
        {
            const __half* g = Alo + (size_t)(mBase + tid) * Cn + k0;
            const u32 sa = sb + TILE_B + so;
            cp16(sa,      g);
            cp16(sa + 16, g + 8);
            cp16(sa + 32, g + 16);
            cp16(sa + 48, g + 24);
        }
        {
            const __half* g = Bm + (size_t)(nBase + tid) * Cn + k0;
            const u32 sa = sb + 2 * TILE_B + so;
            cp16(sa,      g);
            cp16(sa + 16, g + 8);
            cp16(sa + 32, g + 16);
            cp16(sa + 48, g + 24);
        }
        CP_COMMIT();
    };

    load_chunk(0, 0);

    for (int c = 0; c < NCHUNK; c++) {
        const int s = c & 1;
        if (c + 1 < NCHUNK) load_chunk(c + 1, s ^ 1);
        if (c + 1 < NCHUNK) { CP_WAIT(1); } else { CP_WAIT(0); }
        __syncthreads();

        const u32 sb  = sbase + s * STAGE_B;
        const u32 sAh = sb;
        const u32 sAl = sb + TILE_B;
        const u32 sB  = sb + 2 * TILE_B;

#pragma unroll
        for (int k16 = 0; k16 < 2; k16++) {
            const int col = k16 * 16 + (lane >> 4) * 8;
            const int lrow = (lane & 15);

            u32 ahi[4][4], alo[4][4], bfr[4][4];
#pragma unroll
            for (int mt = 0; mt < 4; mt++) {
                int row = wr * 64 + mt * 16 + lrow;
                u32 off = (u32)(row * LDS_H + col) * 2;
                ldsm_x4(ahi[mt][0], ahi[mt][1], ahi[mt][2], ahi[mt][3], sAh + off);
                ldsm_x4(alo[mt][0], alo[mt][1], alo[mt][2], alo[mt][3], sAl + off);
            }
#pragma unroll
            for (int p = 0; p < 4; p++) {
                int row = wc * 64 + p * 16 + lrow;
                u32 off = (u32)(row * LDS_H + col) * 2;
                ldsm_x4(bfr[p][0], bfr[p][1], bfr[p][2], bfr[p][3], sB + off);
            }
            u32 bf2[8][2];
#pragma unroll
            for (int p = 0; p < 4; p++) {
                bf2[2 * p][0]     = bfr[p][0]; bf2[2 * p][1]     = bfr[p][2];
                bf2[2 * p + 1][0] = bfr[p][1]; bf2[2 * p + 1][1] = bfr[p][3];
            }
            // pass-major (hi over all 32 slots, then lo)
#pragma unroll
            for (int pass = 0; pass < 2; pass++) {
#pragma unroll
                for (int mt = 0; mt < 4; mt++) {
                    const u32* A = pass ? alo[mt] : ahi[mt];
#pragma unroll
                    for (int nt = 0; nt < 8; nt++)
                        mma16816h(acc[mt][nt], A, bf2[nt]);
                }
            }
        }
        __syncthreads();
    }

    // ---- epilogue: two 64-col passes through smem
    float* sD = (float*)smem;   // [128][68] = 34816 B
    const int c2  = (tid & 31) * 2;
    const int rr0 = tid >> 5;   // 0..3

#pragma unroll
    for (int hc = 0; hc < 2; hc++) {
        __syncthreads();
        if (wc == hc) {
#pragma unroll
            for (int mt = 0; mt < 4; mt++)
#pragma unroll
                for (int nt = 0; nt < 8; nt++) {
                    int row = wr * 64 + mt * 16 + (lane >> 2);
                    int col = nt * 8 + (lane & 3) * 2;
                    sD[row * 68 + col + 0]       = acc[mt][nt][0];
                    sD[row * 68 + col + 1]       = acc[mt][nt][1];
                    sD[(row + 8) * 68 + col + 0] = acc[mt][nt][2];
                    sD[(row + 8) * 68 + col + 1] = acc[mt][nt][3];
                }
        }
        __syncthreads();

        if (!isOut) {
            const int gcol = nBase + hc * 64 + c2;
            const int h = gcol >> 7;
            const int d = gcol & 127;
#pragma unroll 4
            for (int rr = 0; rr < 32; rr++) {
                int r = rr * 4 + rr0;
                int m = mBase + r;
                int b = m >> 11, t = m & (Tn - 1);
                size_t idx = (size_t)((b * Hn + h) * Tn + t) * HDn + d;
                float v0 = sD[r * 68 + c2];
                float v1 = sD[r * 68 + c2 + 1];
                if (mat == 2) {
                    *(u32*)&g_Vh[idx] = pack_f16x2(v0, v1);
                } else {
                    float h0 = __bfloat162float(__float2bfloat16(v0));
                    float h1 = __bfloat162float(__float2bfloat16(v1));
                    __nv_bfloat16* HI = (mat == 0) ? g_Qhi : g_Khi;
                    __nv_bfloat16* LO = (mat == 0) ? g_Qlo : g_Klo;
                    *(u32*)&HI[idx] = pack_bf16x2(v0, v1);
                    *(u32*)&LO[idx] = pack_bf16x2(v0 - h0, v1 - h1);
                }
            }
        } else {
#pragma unroll 4
            for (int rr = 0; rr < 32; rr++) {
                int r = rr * 4 + rr0;
                int m = mBase + r;
                float2 v = make_float2(sD[r * 68 + c2], sD[r * 68 + c2 + 1]);
                *(float2*)&OutParam[(size_t)m * Cn + nBase + hc * 64 + c2] = v;
            }
        }
    }
}

// ---------------------------------------------------------------------------
// HMMA fused relu-attention, split-precision scores (unchanged from R7).
// ---------------------------------------------------------------------------
constexpr int AT_STR  = 136;
constexpr int AT_Q_B  = 128 * AT_STR * 2;                 // 34816
constexpr int AT_KV_B = 64 * AT_STR * 2;                  // 17408
constexpr int ATTN_SMEM = 2 * AT_Q_B + 6 * AT_KV_B;       // 174080

__global__ __launch_bounds__(256, 1)
void attn_hmma()
{
    extern __shared__ char smem[];
    const u32 sQh = smem_to_u32(smem);
    const u32 sQl = sQh + AT_Q_B;
    const u32 sS0 = sQl + AT_Q_B;
    const u32 sS1 = sS0 + 3 * AT_KV_B;

    const int tid  = threadIdx.x;
    const int lane = tid & 31;
    const int w    = tid >> 5;

    const int qt  = (gridDim.x - 1) - blockIdx.x;
    const int bh  = blockIdx.y;
    const int qg0 = qt * 128;

    const __nv_bfloat16* Qhg = g_Qhi + ((size_t)bh * Tn + qg0) * HDn;
    const __nv_bfloat16* Qlg = g_Qlo + ((size_t)bh * Tn + qg0) * HDn;
    const __nv_bfloat16* Khg = g_Khi + (size_t)bh * Tn * HDn;
    const __nv_bfloat16* Klg = g_Klo + (size_t)bh * Tn * HDn;
    const __half*        Vg  = g_Vh  + (size_t)bh * Tn * HDn;

    auto load_kv = [&](int kt, u32 st) {
        const int kr = tid >> 2, kseg = (tid & 3) * 32;
        const size_t gro = (size_t)(kt * 64 + kr) * HDn;
        const u32 so = (kr * AT_STR + kseg) * 2;
#pragma unroll
        for (int i = 0; i < 4; i++) {
            int c = i * 8;
            cp16(st + so + c * 2,               Khg + gro + kseg + c);
            cp16(st + AT_KV_B + so + c * 2,     Klg + gro + kseg + c);
            cp16(st + 2 * AT_KV_B + so + c * 2, Vg  + gro + kseg + c);
        }
        CP_COMMIT();
    };

    {
        const int r = tid >> 1, cseg = (tid & 1) * 64;
#pragma unroll
        for (int i = 0; i < 8; i++) {
            int col = cseg + i * 8;
            cp16(sQh + (r * AT_STR + col) * 2, Qhg + (size_t)r * HDn + col);
            cp16(sQl + (r * AT_STR + col) * 2, Qlg + (size_t)r * HDn + col);
        }
    }
    load_kv(0, sS0);

    const int ktmax = 2 * qt + 1;

    float o[16][4];
#pragma unroll
    for (int i = 0; i < 16; i++)
#pragma unroll
        for (int r = 0; r < 4; r++) o[i][r] = 0.f;
    float rs0 = 0.f, rs1 = 0.f;

    const int r0 = qg0 + w * 16 + (lane >> 2);
    const int r1 = r0 + 8;

    for (int kt = 0; kt <= ktmax; kt++) {
        if (kt + 1 <= ktmax) {
            load_kv(kt + 1, ((kt + 1) & 1) ? sS1 : sS0);
            CP_WAIT(1);
        } else {
            CP_WAIT(0);
        }
        __syncthreads();

        const u32 st  = (kt & 1) ? sS1 : sS0;
        const u32 cKh = st;
        const u32 cKl = st + AT_KV_B;
        const u32 cV  = st + 2 * AT_KV_B;

        float s[8][4];
#pragma unroll
        for (int i = 0; i < 8; i++)
#pragma unroll
            for (int r = 0; r < 4; r++) s[i][r] = 0.f;

#pragma unroll
        for (int c16 = 0; c16 < 8; c16++) {
            u32 qh[4], ql[4];
            {
                int row = w * 16 + (lane & 15);
                int col = c16 * 16 + (lane >> 4) * 8;
                u32 off = (row * AT_STR + col) * 2;
                ldsm_x4(qh[0], qh[1], qh[2], qh[3], sQh + off);
                ldsm_x4(ql[0], ql[1], ql[2], ql[3], sQl + off);
            }
#pragma unroll
            for (int npp = 0; npp < 2; npp++) {
                u32 kh[2][4], kl[2][4];
#pragma unroll
                for (int q = 0; q < 2; q++) {
                    int np = npp * 2 + q;
                    int row = np * 16 + (lane & 15);
                    int col = c16 * 16 + (lane >> 4) * 8;
                    u32 off = (row * AT_STR + col) * 2;
                    ldsm_x4(kh[q][0], kh[q][1], kh[q][2], kh[q][3], cKh + off);
                    ldsm_x4(kl[q][0], kl[q][1], kl[q][2], kl[q][3], cKl + off);
                }
                u32 bh[4][2], bl[4][2];
#pragma unroll
                for (int q = 0; q < 2; q++) {
                    bh[2 * q][0] = kh[q][0]; bh[2 * q][1] = kh[q][2];
                    bh[2 * q + 1][0] = kh[q][1]; bh[2 * q + 1][1] = kh[q][3];
                    bl[2 * q][0] = kl[q][0]; bl[2 * q][1] = kl[q][2];
                    bl[2 * q + 1][0] = kl[q][1]; bl[2 * q + 1][1] = kl[q][3];
                }
                float* S[4] = { s[4 * npp], s[4 * npp + 1],
                                s[4 * npp + 2], s[4 * npp + 3] };
#pragma unroll
                for (int t = 0; t < 4; t++) mma16816(S[t], qh, bh[t]);
#pragma unroll
                for (int t = 0; t < 4; t++) mma16816(S[t], qh, bl[t]);
#pragma unroll
                for (int t = 0; t < 4; t++) mma16816(S[t], ql, bh[t]);
            }
        }

        const bool diag = (kt >= 2 * qt);
        u32 wf[4][4];
#pragma unroll
        for (int n8 = 0; n8 < 8; n8++) {
            int kg = kt * 64 + n8 * 8 + (lane & 3) * 2;
            float e0 = fmaxf(fmaf(s[n8][0], SCALE, 0.1f), 0.f);
            float e1 = fmaxf(fmaf(s[n8][1], SCALE, 0.1f), 0.f);
            float e2 = fmaxf(fmaf(s[n8][2], SCALE, 0.1f), 0.f);
            float e3 = fmaxf(fmaf(s[n8][3], SCALE, 0.1f), 0.f);
            if (diag) {
                if (kg     > r0) e0 = 0.f;
                if (kg + 1 > r0) e1 = 0.f;
                if (kg     > r1) e2 = 0.f;
                if (kg + 1 > r1) e3 = 0.f;
            }
            rs0 += e0 + e1;
            rs1 += e2 + e3;
            s[n8][0] = e0; s[n8][1] = e1; s[n8][2] = e2; s[n8][3] = e3;
        }
#pragma unroll
        for (int t = 0; t < 4; t++) {
            wf[t][0] = pack_f16x2(s[2 * t][0],     s[2 * t][1]);
            wf[t][1] = pack_f16x2(s[2 * t][2],     s[2 * t][3]);
            wf[t][2] = pack_f16x2(s[2 * t + 1][0], s[2 * t + 1][1]);
            wf[t][3] = pack_f16x2(s[2 * t + 1][2], s[2 * t + 1][3]);
        }

#pragma unroll
        for (int t = 0; t < 4; t++) {
#pragma unroll
            for (int d2 = 0; d2 < 8; d2++) {
                u32 vb[4];
                int row = t * 16 + (lane & 15);
                int col = d2 * 16 + (lane >> 4) * 8;
                ldsm_x4_t(vb[0], vb[1], vb[2], vb[3], cV + (row * AT_STR + col) * 2);
                u32 b0[2] = { vb[0], vb[1] };
                u32 b1[2] = { vb[2], vb[3] };
                mma16816h(o[2 * d2],     wf[t], b0);
                mma16816h(o[2 * d2 + 1], wf[t], b1);
            }
        }
        __syncthreads();
    }

    rs0 += __shfl_xor_sync(0xffffffffu, rs0, 1);
    rs0 += __shfl_xor_sync(0xffffffffu, rs0, 2);
    rs1 += __shfl_xor_sync(0xffffffffu, rs1, 1);
    rs1 += __shfl_xor_sync(0xffffffffu, rs1, 2);
    const float inv0 = 1.f / (rs0 + EPSv);
    const float inv1 = 1.f / (rs1 + EPSv);

    const int b  = bh >> 4, hh = bh & 15;
    const size_t base0 = ((size_t)(b * Tn + r0) * Cn) + hh * 128;
    const size_t base1 = ((size_t)(b * Tn + r1) * Cn) + hh * 128;

#pragma unroll
    for (int d8 = 0; d8 < 16; d8++) {
        int col = d8 * 8 + (lane & 3) * 2;
        float v0 = o[d8][0] * inv0, v1 = o[d8][1] * inv0;
        float u0 = o[d8][2] * inv1, u1 = o[d8][3] * inv1;

        float h0 = __half2float(__float2half(v0));
        float h1 = __half2float(__float2half(v1));
        float g0 = __half2float(__float2half(u0));
        float g1 = __half2float(__float2half(u1));

        *(u32*)&g_Ahi[base0 + col] = pack_f16x2(v0, v1);
        *(u32*)&g_Alo[base0 + col] = pack_f16x2(v0 - h0, v1 - h1);
        *(u32*)&g_Ahi[base1 + col] = pack_f16x2(u0, u1);
        *(u32*)&g_Alo[base1 + col] = pack_f16x2(u0 - g0, u1 - g1);
    }
}

// ---------------------------------------------------------------------------

extern "C" void kernel_launch(void* const* d_in, const int* in_sizes, int n_in,
                              void* d_out, int out_size)
{
    const float* x  = (const float*)d_in[0];
    const float* Wq = (const float*)d_in[1];
    const float* Wk = (const float*)d_in[2];
    const float* Wv = (const float*)d_in[3];
    const float* Wo = (const float*)d_in[4];
    float* out = (float*)d_out;

    cudaFuncSetAttribute(gemm_f16,
                         cudaFuncAttributeMaxDynamicSharedMemorySize, GEMM_SMEM);
    cudaFuncSetAttribute(attn_hmma,
                         cudaFuncAttributeMaxDynamicSharedMemorySize, ATTN_SMEM);

    const int nX = Bn * Tn * Cn;
    const int nW = Cn * Cn;

    // order chosen so ncu (-s 5 -c 1) profiles gemm_f16 next round
    conv_w_kernel<<<(nW / 4 + 255) / 256, 256>>>(Wq, 0, nW);
    conv_w_kernel<<<(nW / 4 + 255) / 256, 256>>>(Wk, 1, nW);
    conv_w_kernel<<<(nW / 4 + 255) / 256, 256>>>(Wv, 2, nW);
    conv_w_kernel<<<(nW / 4 + 255) / 256, 256>>>(Wo, 3, nW);
    split_x_kernel<<<(nX / 4 + 255) / 256, 256>>>(x, nX);

    dim3 gQKV(Cn / 128, (Bn * Tn) / 128, 3);
    gemm_f16<<<gQKV, 128, GEMM_SMEM>>>(0, nullptr);

    dim3 gAttn(Tn / 128, Bn * Hn);
    attn_hmma<<<gAttn, 256, ATTN_SMEM>>>();

    dim3 gOut(Cn / 128, (Bn * Tn) / 128, 1);
    gemm_f16<<<gOut, 128, GEMM_SMEM>>>(1, out);
}

// round 11
// speedup vs baseline: 1.5978x; 1.5978x over previous
#include <cuda_runtime.h>
#include <cuda_bf16.h>
#include <cuda_fp16.h>

typedef unsigned int       u32;
typedef unsigned long long u64;

// Problem constants
constexpr int Bn  = 2;
constexpr int Tn  = 2048;
constexpr int Cn  = 2048;
constexpr int Hn  = 16;
constexpr int HDn = 128;
constexpr float SCALE = 0.088388347648318447f;   // 1/sqrt(128)
constexpr float EPSv  = 1e-6f;

// ---------------------------------------------------------------------------
// Device-global scratch
// ---------------------------------------------------------------------------
__device__ __half g_Qhi[(size_t)Bn * Hn * Tn * HDn];  // [B,H,T,hd] fp16 hi/lo
__device__ __half g_Qlo[(size_t)Bn * Hn * Tn * HDn];
__device__ __half g_Kh [(size_t)Bn * Hn * Tn * HDn];  // fp16 single
__device__ __half g_Vh [(size_t)Bn * Hn * Tn * HDn];  // fp16 single

__device__ __half g_Xhi[(size_t)Bn * Tn * Cn];
__device__ __half g_Xlo[(size_t)Bn * Tn * Cn];
__device__ __half g_Wh[4][(size_t)Cn * Cn];
__device__ __half g_Ah[(size_t)Bn * Tn * Cn];         // attn out fp16 single

// ---------------------------------------------------------------------------
// PTX helpers
// ---------------------------------------------------------------------------
__device__ __forceinline__ u32 smem_to_u32(const void* p) {
    u32 a;
    asm("{ .reg .u64 t; cvta.to.shared.u64 t, %1; cvt.u32.u64 %0, t; }"
        : "=r"(a) : "l"(p));
    return a;
}

__device__ __forceinline__ void cp16(u32 saddr, const void* g) {
    asm volatile("cp.async.cg.shared.global [%0], [%1], 16;"
                 :: "r"(saddr), "l"(g) : "memory");
}
#define CP_COMMIT() asm volatile("cp.async.commit_group;" ::: "memory")
#define CP_WAIT(n)  asm volatile("cp.async.wait_group %0;" :: "n"(n) : "memory")

__device__ __forceinline__ void ldsm_x4(u32& r0, u32& r1, u32& r2, u32& r3, u32 addr) {
    asm volatile("ldmatrix.sync.aligned.m8n8.x4.shared.b16 {%0,%1,%2,%3}, [%4];"
                 : "=r"(r0), "=r"(r1), "=r"(r2), "=r"(r3) : "r"(addr));
}
__device__ __forceinline__ void ldsm_x4_t(u32& r0, u32& r1, u32& r2, u32& r3, u32 addr) {
    asm volatile("ldmatrix.sync.aligned.m8n8.x4.trans.shared.b16 {%0,%1,%2,%3}, [%4];"
                 : "=r"(r0), "=r"(r1), "=r"(r2), "=r"(r3) : "r"(addr));
}
__device__ __forceinline__ void ldsm_x2(u32& r0, u32& r1, u32 addr) {
    asm volatile("ldmatrix.sync.aligned.m8n8.x2.shared.b16 {%0,%1}, [%2];"
                 : "=r"(r0), "=r"(r1) : "r"(addr));
}

__device__ __forceinline__ void mma16816h(float* d, const u32* a, const u32* b) {
    asm volatile(
        "mma.sync.aligned.m16n8k16.row.col.f32.f16.f16.f32 "
        "{%0,%1,%2,%3}, {%4,%5,%6,%7}, {%8,%9}, {%0,%1,%2,%3};"
        : "+f"(d[0]), "+f"(d[1]), "+f"(d[2]), "+f"(d[3])
        : "r"(a[0]), "r"(a[1]), "r"(a[2]), "r"(a[3]), "r"(b[0]), "r"(b[1]));
}

// pack {lo, hi} floats (lo -> bits[15:0])
__device__ __forceinline__ u32 pack_f16x2(float lo, float hi) {
    u32 r;
    asm("cvt.rn.f16x2.f32 %0, %1, %2;" : "=r"(r) : "f"(hi), "f"(lo));
    return r;
}

// ---------------------------------------------------------------------------
// fp32 -> fp16 hi/lo split of X
// ---------------------------------------------------------------------------
__global__ void split_x_kernel(const float* __restrict__ in, int n)
{
    int i = (blockIdx.x * blockDim.x + threadIdx.x) * 4;
    if (i >= n) return;
    float4 v = *(const float4*)(in + i);
    __half h0 = __float2half(v.x), h1 = __float2half(v.y);
    __half h2 = __float2half(v.z), h3 = __float2half(v.w);
    __half l0 = __float2half(v.x - __half2float(h0));
    __half l1 = __float2half(v.y - __half2float(h1));
    __half l2 = __float2half(v.z - __half2float(h2));
    __half l3 = __float2half(v.w - __half2float(h3));
    __half2* hp = (__half2*)(g_Xhi + i);
    __half2* lp = (__half2*)(g_Xlo + i);
    hp[0] = __halves2half2(h0, h1); hp[1] = __halves2half2(h2, h3);
    lp[0] = __halves2half2(l0, l1); lp[1] = __halves2half2(l2, l3);
}

// fp32 -> fp16 single conversion of a weight matrix
__global__ void conv_w_kernel(const float* __restrict__ in, int which, int n)
{
    int i = (blockIdx.x * blockDim.x + threadIdx.x) * 4;
    if (i >= n) return;
    float4 v = *(const float4*)(in + i);
    __half2* p = (__half2*)(g_Wh[which] + i);
    p[0] = __halves2half2(__float2half(v.x), __float2half(v.y));
    p[1] = __halves2half2(__float2half(v.z), __float2half(v.w));
}

// ---------------------------------------------------------------------------
// HMMA fp16 GEMM (R7 schedule): out[m,n] = sum_k A[m,k] * W[n,k]
// Block 128x128, BK=32, 8 warps (2x4), warp tile 64x32, double-buffered,
// 2 CTAs/SM. Q,K projections: 2-pass (Ahi+Alo); V / out-proj: single pass.
// isOut==0: A=X, B=W[z]; out -> Qhi/Qlo fp16 (z=0), Kh (z=1), Vh (z=2)
// isOut==1: A=g_Ah (single), B=Wo; out -> fp32 OutParam
// ---------------------------------------------------------------------------
constexpr int GBK     = 32;
constexpr int LDS_H   = 40;
constexpr int TILE_B  = 128 * LDS_H * 2;          // 10240
constexpr int STAGE_B = 3 * TILE_B;               // 30720
constexpr int GEMM_SMEM = 2 * STAGE_B;            // 61440
constexpr int NCHUNK  = Cn / GBK;                 // 64

__global__ __launch_bounds__(256, 2)
void gemm_f16(int isOut, float* __restrict__ OutParam)
{
    extern __shared__ char smem[];
    const u32 sbase = smem_to_u32(smem);
    const int tid  = threadIdx.x;
    const int lane = tid & 31;
    const int warp = tid >> 5;
    const int wr   = warp >> 2;     // 0..1
    const int wc   = warp & 3;      // 0..3

    const int mat = isOut ? 3 : blockIdx.z;
    const bool twoPass = (!isOut) && (mat <= 1);   // Q, K projections
    const __half* __restrict__ Ahi = isOut ? g_Ah : g_Xhi;
    const __half* __restrict__ Alo = g_Xlo;        // used only when twoPass
    const __half* __restrict__ Bm  = g_Wh[mat];

    const int mBase = blockIdx.y * 128;
    const int nBase = blockIdx.x * 128;

    float acc[4][4][4];
#pragma unroll
    for (int i = 0; i < 4; i++)
#pragma unroll
        for (int j = 0; j < 4; j++)
#pragma unroll
            for (int r = 0; r < 4; r++) acc[i][j][r] = 0.f;

    const int ldr = tid >> 1;
    const int ldc = (tid & 1) * 16;

    auto load_chunk = [&](int kc, int s) {
        const u32 sb = sbase + s * STAGE_B;
        const int k0 = kc * GBK;
        {
            const __half* g = Ahi + (size_t)(mBase + ldr) * Cn + k0 + ldc;
            u32 sa = sb + (ldr * LDS_H + ldc) * 2;
            cp16(sa,      g);
            cp16(sa + 16, g + 8);
        }
        if (twoPass) {
            const __half* g = Alo + (size_t)(mBase + ldr) * Cn + k0 + ldc;
            u32 sa = sb + TILE_B + (ldr * LDS_H + ldc) * 2;
            cp16(sa,      g);
            cp16(sa + 16, g + 8);
        }
        {
            const __half* g = Bm + (size_t)(nBase + ldr) * Cn + k0 + ldc;
            u32 sa = sb + 2 * TILE_B + (ldr * LDS_H + ldc) * 2;
            cp16(sa,      g);
            cp16(sa + 16, g + 8);
        }
        CP_COMMIT();
    };

    load_chunk(0, 0);

    for (int c = 0; c < NCHUNK; c++) {
        const int s = c & 1;
        if (c + 1 < NCHUNK) load_chunk(c + 1, s ^ 1);
        if (c + 1 < NCHUNK) { CP_WAIT(1); } else { CP_WAIT(0); }
        __syncthreads();

        const u32 sb  = sbase + s * STAGE_B;
        const u32 sAh = sb;
        const u32 sAl = sb + TILE_B;
        const u32 sB  = sb + 2 * TILE_B;

#pragma unroll
        for (int k16 = 0; k16 < 2; k16++) {
            const int col = k16 * 16 + (lane >> 4) * 8;
            const int lrow = (lane & 15);

            u32 ahi[4][4], alo[4][4], bfr[2][4];
#pragma unroll
            for (int mt = 0; mt < 4; mt++) {
                int row = wr * 64 + mt * 16 + lrow;
                u32 off = (u32)(row * LDS_H + col) * 2;
                ldsm_x4(ahi[mt][0], ahi[mt][1], ahi[mt][2], ahi[mt][3], sAh + off);
                if (twoPass)
                    ldsm_x4(alo[mt][0], alo[mt][1], alo[mt][2], alo[mt][3], sAl + off);
            }
#pragma unroll
            for (int p = 0; p < 2; p++) {
                int row = wc * 32 + p * 16 + lrow;
                u32 off = (u32)(row * LDS_H + col) * 2;
                ldsm_x4(bfr[p][0], bfr[p][1], bfr[p][2], bfr[p][3], sB + off);
            }
            u32 b0[2][2], b1[2][2];
#pragma unroll
            for (int p = 0; p < 2; p++) {
                b0[p][0] = bfr[p][0]; b0[p][1] = bfr[p][2];
                b1[p][0] = bfr[p][1]; b1[p][1] = bfr[p][3];
            }
            // hi pass (all 16 slots)
#pragma unroll
            for (int mt = 0; mt < 4; mt++)
#pragma unroll
                for (int p = 0; p < 2; p++) {
                    mma16816h(acc[mt][2 * p],     ahi[mt], b0[p]);
                    mma16816h(acc[mt][2 * p + 1], ahi[mt], b1[p]);
                }
            // lo pass
            if (twoPass) {
#pragma unroll
                for (int mt = 0; mt < 4; mt++)
#pragma unroll
                    for (int p = 0; p < 2; p++) {
                        mma16816h(acc[mt][2 * p],     alo[mt], b0[p]);
                        mma16816h(acc[mt][2 * p + 1], alo[mt], b1[p]);
                    }
            }
        }
        __syncthreads();
    }

    // ---- epilogue: two 64-col half passes through smem
    float* sD = (float*)smem;   // [128][68] = 34816 B
    const int c2  = (tid & 31) * 2;
    const int rr0 = tid >> 5;   // 0..7

#pragma unroll
    for (int hc = 0; hc < 2; hc++) {
        __syncthreads();
        if ((wc >> 1) == hc) {
#pragma unroll
            for (int mt = 0; mt < 4; mt++)
#pragma unroll
                for (int nt = 0; nt < 4; nt++) {
                    int row = wr * 64 + mt * 16 + (lane >> 2);
                    int col = (wc & 1) * 32 + nt * 8 + (lane & 3) * 2;
                    sD[row * 68 + col + 0]       = acc[mt][nt][0];
                    sD[row * 68 + col + 1]       = acc[mt][nt][1];
                    sD[(row + 8) * 68 + col + 0] = acc[mt][nt][2];
                    sD[(row + 8) * 68 + col + 1] = acc[mt][nt][3];
                }
        }
        __syncthreads();

        if (!isOut) {
            const int h = blockIdx.x;      // BN == hd == 128
            const int d = hc * 64 + c2;
#pragma unroll 4
            for (int rr = 0; rr < 16; rr++) {
                int r = rr * 8 + rr0;
                int m = mBase + r;
                int b = m >> 11, t = m & (Tn - 1);
                size_t idx = (size_t)((b * Hn + h) * Tn + t) * HDn + d;
                float v0 = sD[r * 68 + c2];
                float v1 = sD[r * 68 + c2 + 1];
                if (mat == 0) {
                    float h0 = __half2float(__float2half(v0));
                    float h1 = __half2float(__float2half(v1));
                    *(u32*)&g_Qhi[idx] = pack_f16x2(v0, v1);
                    *(u32*)&g_Qlo[idx] = pack_f16x2(v0 - h0, v1 - h1);
                } else if (mat == 1) {
                    *(u32*)&g_Kh[idx] = pack_f16x2(v0, v1);
                } else {
                    *(u32*)&g_Vh[idx] = pack_f16x2(v0, v1);
                }
            }
        } else {
#pragma unroll 4
            for (int rr = 0; rr < 16; rr++) {
                int r = rr * 8 + rr0;
                int m = mBase + r;
                float2 v = make_float2(sD[r * 68 + c2], sD[r * 68 + c2 + 1]);
                *(float2*)&OutParam[(size_t)m * Cn + nBase + hc * 64 + c2] = v;
            }
        }
    }
}

// ---------------------------------------------------------------------------
// HMMA fused relu-attention.
// S = (Qhi + Qlo) * K : fp16 2-pass (Q split fp16, K single fp16).
// W(fp16) @ V(fp16) single pass. Q fragments hoisted out of the kt loop.
// Block: 128 q-rows x (b,h). 8 warps x 16 q-rows. 64-row K/V tiles, dbl-buf.
// ---------------------------------------------------------------------------
constexpr int AT_STR  = 136;
constexpr int AT_Q_B  = 128 * AT_STR * 2;                 // 34816
constexpr int AT_KV_B = 64 * AT_STR * 2;                  // 17408
// layout: Qhi, Qlo, stage0{K,V}, stage1{K,V}
constexpr int ATTN_SMEM = 2 * AT_Q_B + 4 * AT_KV_B;       // 139264

__global__ __launch_bounds__(256, 1)
void attn_hmma()
{
    extern __shared__ char smem[];
    const u32 sQh = smem_to_u32(smem);
    const u32 sQl = sQh + AT_Q_B;
    const u32 sS0 = sQl + AT_Q_B;
    const u32 sS1 = sS0 + 2 * AT_KV_B;

    const int tid  = threadIdx.x;
    const int lane = tid & 31;
    const int w    = tid >> 5;

    const int qt  = (gridDim.x - 1) - blockIdx.x;
    const int bh  = blockIdx.y;
    const int qg0 = qt * 128;

    const __half* Qhg = g_Qhi + ((size_t)bh * Tn + qg0) * HDn;
    const __half* Qlg = g_Qlo + ((size_t)bh * Tn + qg0) * HDn;
    const __half* Kg  = g_Kh  + (size_t)bh * Tn * HDn;
    const __half* Vg  = g_Vh  + (size_t)bh * Tn * HDn;

    auto load_kv = [&](int kt, u32 st) {
        const int kr = tid >> 2, kseg = (tid & 3) * 32;
        const size_t gro = (size_t)(kt * 64 + kr) * HDn;
        const u32 so = (kr * AT_STR + kseg) * 2;
#pragma unroll
        for (int i = 0; i < 4; i++) {
            int c = i * 8;
            cp16(st + so + c * 2,            Kg + gro + kseg + c);
            cp16(st + AT_KV_B + so + c * 2,  Vg + gro + kseg + c);
        }
        CP_COMMIT();
    };

    // ---- prologue: Q hi/lo (group A), then KV tile 0 (group B)
    {
        const int r = tid >> 1, cseg = (tid & 1) * 64;
#pragma unroll
        for (int i = 0; i < 8; i++) {
            int col = cseg + i * 8;
            cp16(sQh + (r * AT_STR + col) * 2, Qhg + (size_t)r * HDn + col);
            cp16(sQl + (r * AT_STR + col) * 2, Qlg + (size_t)r * HDn + col);
        }
        CP_COMMIT();
    }
    load_kv(0, sS0);

    // wait for Q (allow KV0 pending), then hoist Q fragments to registers
    CP_WAIT(1);
    __syncthreads();

    u32 qh[8][4], ql[8][4];
    {
        const int row = w * 16 + (lane & 15);
#pragma unroll
        for (int c16 = 0; c16 < 8; c16++) {
            int col = c16 * 16 + (lane >> 4) * 8;
            u32 off = (u32)(row * AT_STR + col) * 2;
            ldsm_x4(qh[c16][0], qh[c16][1], qh[c16][2], qh[c16][3], sQh + off);
            ldsm_x4(ql[c16][0], ql[c16][1], ql[c16][2], ql[c16][3], sQl + off);
        }
    }

    const int ktmax = 2 * qt + 1;

    float o[16][4];
#pragma unroll
    for (int i = 0; i < 16; i++)
#pragma unroll
        for (int r = 0; r < 4; r++) o[i][r] = 0.f;
    float rs0 = 0.f, rs1 = 0.f;

    const int r0 = qg0 + w * 16 + (lane >> 2);
    const int r1 = r0 + 8;

    for (int kt = 0; kt <= ktmax; kt++) {
        if (kt + 1 <= ktmax) {
            load_kv(kt + 1, ((kt + 1) & 1) ? sS1 : sS0);
            CP_WAIT(1);
        } else {
            CP_WAIT(0);
        }
        __syncthreads();

        const u32 st = (kt & 1) ? sS1 : sS0;
        const u32 cK = st;
        const u32 cV = st + AT_KV_B;

        // ---- S = Q K^T, fp16 2-pass (hi then lo), warp: 16 x 64
        float s[8][4];
#pragma unroll
        for (int i = 0; i < 8; i++)
#pragma unroll
            for (int r = 0; r < 4; r++) s[i][r] = 0.f;

#pragma unroll
        for (int c16 = 0; c16 < 8; c16++) {
            u32 kb[4][4];
#pragma unroll
            for (int np = 0; np < 4; np++) {
                int row = np * 16 + (lane & 15);
                int col = c16 * 16 + (lane >> 4) * 8;
                u32 off = (u32)(row * AT_STR + col) * 2;
                ldsm_x4(kb[np][0], kb[np][1], kb[np][2], kb[np][3], cK + off);
            }
            u32 b2[8][2];
#pragma unroll
            for (int np = 0; np < 4; np++) {
                b2[2 * np][0]     = kb[np][0]; b2[2 * np][1]     = kb[np][2];
                b2[2 * np + 1][0] = kb[np][1]; b2[2 * np + 1][1] = kb[np][3];
            }
#pragma unroll
            for (int t = 0; t < 8; t++) mma16816h(s[t], qh[c16], b2[t]);
#pragma unroll
            for (int t = 0; t < 8; t++) mma16816h(s[t], ql[c16], b2[t]);
        }

        // ---- relu + mask + rowsum; pack as fp16 A-frags
        const bool diag = (kt >= 2 * qt);
        u32 wf[4][4];
#pragma unroll
        for (int n8 = 0; n8 < 8; n8++) {
            int kg = kt * 64 + n8 * 8 + (lane & 3) * 2;
            float e0 = fmaxf(fmaf(s[n8][0], SCALE, 0.1f), 0.f);
            float e1 = fmaxf(fmaf(s[n8][1], SCALE, 0.1f), 0.f);
            float e2 = fmaxf(fmaf(s[n8][2], SCALE, 0.1f), 0.f);
            float e3 = fmaxf(fmaf(s[n8][3], SCALE, 0.1f), 0.f);
            if (diag) {
                if (kg     > r0) e0 = 0.f;
                if (kg + 1 > r0) e1 = 0.f;
                if (kg     > r1) e2 = 0.f;
                if (kg + 1 > r1) e3 = 0.f;
            }
            rs0 += e0 + e1;
            rs1 += e2 + e3;
            s[n8][0] = e0; s[n8][1] = e1; s[n8][2] = e2; s[n8][3] = e3;
        }
#pragma unroll
        for (int t = 0; t < 4; t++) {
            wf[t][0] = pack_f16x2(s[2 * t][0],     s[2 * t][1]);
            wf[t][1] = pack_f16x2(s[2 * t][2],     s[2 * t][3]);
            wf[t][2] = pack_f16x2(s[2 * t + 1][0], s[2 * t + 1][1]);
            wf[t][3] = pack_f16x2(s[2 * t + 1][2], s[2 * t + 1][3]);
        }

        // ---- O += W V   (fp16, warp: 16 x 128, k = 64)
#pragma unroll
        for (int t = 0; t < 4; t++) {
#pragma unroll
            for (int d2 = 0; d2 < 8; d2++) {
                u32 vb[4];
                int row = t * 16 + (lane & 15);
                int col = d2 * 16 + (lane >> 4) * 8;
                ldsm_x4_t(vb[0], vb[1], vb[2], vb[3], cV + (row * AT_STR + col) * 2);
                u32 b0[2] = { vb[0], vb[1] };
                u32 b1[2] = { vb[2], vb[3] };
                mma16816h(o[2 * d2],     wf[t], b0);
                mma16816h(o[2 * d2 + 1], wf[t], b1);
            }
        }
        __syncthreads();
    }

    // ---- rowsum reduce, normalize, store fp16 single
    rs0 += __shfl_xor_sync(0xffffffffu, rs0, 1);
    rs0 += __shfl_xor_sync(0xffffffffu, rs0, 2);
    rs1 += __shfl_xor_sync(0xffffffffu, rs1, 1);
    rs1 += __shfl_xor_sync(0xffffffffu, rs1, 2);
    const float inv0 = 1.f / (rs0 + EPSv);
    const float inv1 = 1.f / (rs1 + EPSv);

    const int b  = bh >> 4, hh = bh & 15;
    const size_t base0 = ((size_t)(b * Tn + r0) * Cn) + hh * 128;
    const size_t base1 = ((size_t)(b * Tn + r1) * Cn) + hh * 128;

#pragma unroll
    for (int d8 = 0; d8 < 16; d8++) {
        int col = d8 * 8 + (lane & 3) * 2;
        float v0 = o[d8][0] * inv0, v1 = o[d8][1] * inv0;
        float u0 = o[d8][2] * inv1, u1 = o[d8][3] * inv1;
        *(u32*)&g_Ah[base0 + col] = pack_f16x2(v0, v1);
        *(u32*)&g_Ah[base1 + col] = pack_f16x2(u0, u1);
    }
}

// ---------------------------------------------------------------------------

extern "C" void kernel_launch(void* const* d_in, const int* in_sizes, int n_in,
                              void* d_out, int out_size)
{
    const float* x  = (const float*)d_in[0];
    const float* Wq = (const float*)d_in[1];
    const float* Wk = (const float*)d_in[2];
    const float* Wv = (const float*)d_in[3];
    const float* Wo = (const float*)d_in[4];
    float* out = (float*)d_out;

    cudaFuncSetAttribute(gemm_f16,
                         cudaFuncAttributeMaxDynamicSharedMemorySize, GEMM_SMEM);
    cudaFuncSetAttribute(attn_hmma,
                         cudaFuncAttributeMaxDynamicSharedMemorySize, ATTN_SMEM);

    const int nX = Bn * Tn * Cn;
    const int nW = Cn * Cn;

    conv_w_kernel<<<(nW / 4 + 255) / 256, 256>>>(Wq, 0, nW);
    conv_w_kernel<<<(nW / 4 + 255) / 256, 256>>>(Wk, 1, nW);
    conv_w_kernel<<<(nW / 4 + 255) / 256, 256>>>(Wv, 2, nW);
    conv_w_kernel<<<(nW / 4 + 255) / 256, 256>>>(Wo, 3, nW);
    split_x_kernel<<<(nX / 4 + 255) / 256, 256>>>(x, nX);

    dim3 gQKV(Cn / 128, (Bn * Tn) / 128, 3);
    gemm_f16<<<gQKV, 256, GEMM_SMEM>>>(0, nullptr);

    dim3 gAttn(Tn / 128, Bn * Hn);
    attn_hmma<<<gAttn, 256, ATTN_SMEM>>>();

    dim3 gOut(Cn / 128, (Bn * Tn) / 128, 1);
    gemm_f16<<<gOut, 256, GEMM_SMEM>>>(1, out);
}

// round 12
// speedup vs baseline: 1.7484x; 1.0943x over previous
#include <cuda_runtime.h>
#include <cuda_bf16.h>
#include <cuda_fp16.h>

typedef unsigned int       u32;
typedef unsigned long long u64;

// Problem constants
constexpr int Bn  = 2;
constexpr int Tn  = 2048;
constexpr int Cn  = 2048;
constexpr int Hn  = 16;
constexpr int HDn = 128;
constexpr float SCALE = 0.088388347648318447f;   // 1/sqrt(128)
constexpr float EPSv  = 1e-6f;

// ---------------------------------------------------------------------------
// Device-global scratch
// ---------------------------------------------------------------------------
__device__ __half g_Qhi[(size_t)Bn * Hn * Tn * HDn];  // [B,H,T,hd] fp16 hi/lo
__device__ __half g_Qlo[(size_t)Bn * Hn * Tn * HDn];
__device__ __half g_Kh [(size_t)Bn * Hn * Tn * HDn];  // fp16 single
__device__ __half g_Vh [(size_t)Bn * Hn * Tn * HDn];  // fp16 single

__device__ __half g_Xhi[(size_t)Bn * Tn * Cn];
__device__ __half g_Xlo[(size_t)Bn * Tn * Cn];
__device__ __half g_Wh[4][(size_t)Cn * Cn];
__device__ __half g_Ah[(size_t)Bn * Tn * Cn];         // attn out fp16 single

// ---------------------------------------------------------------------------
// PTX helpers
// ---------------------------------------------------------------------------
__device__ __forceinline__ u32 smem_to_u32(const void* p) {
    u32 a;
    asm("{ .reg .u64 t; cvta.to.shared.u64 t, %1; cvt.u32.u64 %0, t; }"
        : "=r"(a) : "l"(p));
    return a;
}

__device__ __forceinline__ void cp16(u32 saddr, const void* g) {
    asm volatile("cp.async.cg.shared.global [%0], [%1], 16;"
                 :: "r"(saddr), "l"(g) : "memory");
}
#define CP_COMMIT() asm volatile("cp.async.commit_group;" ::: "memory")
#define CP_WAIT(n)  asm volatile("cp.async.wait_group %0;" :: "n"(n) : "memory")

__device__ __forceinline__ void ldsm_x4(u32& r0, u32& r1, u32& r2, u32& r3, u32 addr) {
    asm volatile("ldmatrix.sync.aligned.m8n8.x4.shared.b16 {%0,%1,%2,%3}, [%4];"
                 : "=r"(r0), "=r"(r1), "=r"(r2), "=r"(r3) : "r"(addr));
}
__device__ __forceinline__ void ldsm_x4_t(u32& r0, u32& r1, u32& r2, u32& r3, u32 addr) {
    asm volatile("ldmatrix.sync.aligned.m8n8.x4.trans.shared.b16 {%0,%1,%2,%3}, [%4];"
                 : "=r"(r0), "=r"(r1), "=r"(r2), "=r"(r3) : "r"(addr));
}

__device__ __forceinline__ void mma16816h(float* d, const u32* a, const u32* b) {
    asm volatile(
        "mma.sync.aligned.m16n8k16.row.col.f32.f16.f16.f32 "
        "{%0,%1,%2,%3}, {%4,%5,%6,%7}, {%8,%9}, {%0,%1,%2,%3};"
        : "+f"(d[0]), "+f"(d[1]), "+f"(d[2]), "+f"(d[3])
        : "r"(a[0]), "r"(a[1]), "r"(a[2]), "r"(a[3]), "r"(b[0]), "r"(b[1]));
}

// pack {lo, hi} floats (lo -> bits[15:0])
__device__ __forceinline__ u32 pack_f16x2(float lo, float hi) {
    u32 r;
    asm("cvt.rn.f16x2.f32 %0, %1, %2;" : "=r"(r) : "f"(hi), "f"(lo));
    return r;
}

// ---------------------------------------------------------------------------
// Fused prologue: convert Wq/Wk/Wv/Wo to fp16 and split X into fp16 hi/lo.
// One launch; linear index space [0, 4*nW4) = weights, [4*nW4, total) = X.
// ---------------------------------------------------------------------------
__global__ void prep_kernel(const float* __restrict__ x,
                            const float* __restrict__ Wq,
                            const float* __restrict__ Wk,
                            const float* __restrict__ Wv,
                            const float* __restrict__ Wo)
{
    const int nW4 = (Cn * Cn) / 4;          // 1048576 float4s per W
    const int nX4 = (Bn * Tn * Cn) / 4;     // 2097152 float4s for X
    const int total = 4 * nW4 + nX4;
    int g = blockIdx.x * blockDim.x + threadIdx.x;
    if (g >= total) return;

    if (g < 4 * nW4) {
        int which = g / nW4;
        int i = (g - which * nW4) * 4;
        const float* in = (which == 0) ? Wq : (which == 1) ? Wk
                        : (which == 2) ? Wv : Wo;
        float4 v = *(const float4*)(in + i);
        __half2* p = (__half2*)(g_Wh[which] + i);
        p[0] = __halves2half2(__float2half(v.x), __float2half(v.y));
        p[1] = __halves2half2(__float2half(v.z), __float2half(v.w));
    } else {
        int i = (g - 4 * nW4) * 4;
        float4 v = *(const float4*)(x + i);
        __half h0 = __float2half(v.x), h1 = __float2half(v.y);
        __half h2 = __float2half(v.z), h3 = __float2half(v.w);
        __half l0 = __float2half(v.x - __half2float(h0));
        __half l1 = __float2half(v.y - __half2float(h1));
        __half l2 = __float2half(v.z - __half2float(h2));
        __half l3 = __float2half(v.w - __half2float(h3));
        __half2* hp = (__half2*)(g_Xhi + i);
        __half2* lp = (__half2*)(g_Xlo + i);
        hp[0] = __halves2half2(h0, h1); hp[1] = __halves2half2(h2, h3);
        lp[0] = __halves2half2(l0, l1); lp[1] = __halves2half2(l2, l3);
    }
}

// ---------------------------------------------------------------------------
// HMMA fp16 GEMM (R7 schedule): out[m,n] = sum_k A[m,k] * W[n,k]
// Block 128x128, BK=32, 8 warps (2x4), warp tile 64x32, double-buffered,
// 2 CTAs/SM. Q projection: 2-pass (Xhi+Xlo); K,V, out-proj: single pass.
// isOut==0: A=X, B=W[z]; out -> Qhi/Qlo fp16 (z=0), Kh (z=1), Vh (z=2)
// isOut==1: A=g_Ah (single), B=Wo; out -> fp32 OutParam
// ---------------------------------------------------------------------------
constexpr int GBK     = 32;
constexpr int LDS_H   = 40;
constexpr int TILE_B  = 128 * LDS_H * 2;          // 10240
constexpr int STAGE_B = 3 * TILE_B;               // 30720
constexpr int GEMM_SMEM = 2 * STAGE_B;            // 61440
constexpr int NCHUNK  = Cn / GBK;                 // 64

__global__ __launch_bounds__(256, 2)
void gemm_f16(int isOut, float* __restrict__ OutParam)
{
    extern __shared__ char smem[];
    const u32 sbase = smem_to_u32(smem);
    const int tid  = threadIdx.x;
    const int lane = tid & 31;
    const int warp = tid >> 5;
    const int wr   = warp >> 2;     // 0..1
    const int wc   = warp & 3;      // 0..3

    const int mat = isOut ? 3 : blockIdx.z;
    const bool twoPass = (!isOut) && (mat == 0);   // Q projection only
    const __half* __restrict__ Ahi = isOut ? g_Ah : g_Xhi;
    const __half* __restrict__ Alo = g_Xlo;        // used only when twoPass
    const __half* __restrict__ Bm  = g_Wh[mat];

    const int mBase = blockIdx.y * 128;
    const int nBase = blockIdx.x * 128;

    float acc[4][4][4];
#pragma unroll
    for (int i = 0; i < 4; i++)
#pragma unroll
        for (int j = 0; j < 4; j++)
#pragma unroll
            for (int r = 0; r < 4; r++) acc[i][j][r] = 0.f;

    const int ldr = tid >> 1;
    const int ldc = (tid & 1) * 16;

    auto load_chunk = [&](int kc, int s) {
        const u32 sb = sbase + s * STAGE_B;
        const int k0 = kc * GBK;
        {
            const __half* g = Ahi + (size_t)(mBase + ldr) * Cn + k0 + ldc;
            u32 sa = sb + (ldr * LDS_H + ldc) * 2;
            cp16(sa,      g);
            cp16(sa + 16, g + 8);
        }
        if (twoPass) {
            const __half* g = Alo + (size_t)(mBase + ldr) * Cn + k0 + ldc;
            u32 sa = sb + TILE_B + (ldr * LDS_H + ldc) * 2;
            cp16(sa,      g);
            cp16(sa + 16, g + 8);
        }
        {
            const __half* g = Bm + (size_t)(nBase + ldr) * Cn + k0 + ldc;
            u32 sa = sb + 2 * TILE_B + (ldr * LDS_H + ldc) * 2;
            cp16(sa,      g);
            cp16(sa + 16, g + 8);
        }
        CP_COMMIT();
    };

    load_chunk(0, 0);

    for (int c = 0; c < NCHUNK; c++) {
        const int s = c & 1;
        if (c + 1 < NCHUNK) load_chunk(c + 1, s ^ 1);
        if (c + 1 < NCHUNK) { CP_WAIT(1); } else { CP_WAIT(0); }
        __syncthreads();

        const u32 sb  = sbase + s * STAGE_B;
        const u32 sAh = sb;
        const u32 sAl = sb + TILE_B;
        const u32 sB  = sb + 2 * TILE_B;

#pragma unroll
        for (int k16 = 0; k16 < 2; k16++) {
            const int col = k16 * 16 + (lane >> 4) * 8;
            const int lrow = (lane & 15);

            u32 ahi[4][4], alo[4][4], bfr[2][4];
#pragma unroll
            for (int mt = 0; mt < 4; mt++) {
                int row = wr * 64 + mt * 16 + lrow;
                u32 off = (u32)(row * LDS_H + col) * 2;
                ldsm_x4(ahi[mt][0], ahi[mt][1], ahi[mt][2], ahi[mt][3], sAh + off);
                if (twoPass)
                    ldsm_x4(alo[mt][0], alo[mt][1], alo[mt][2], alo[mt][3], sAl + off);
            }
#pragma unroll
            for (int p = 0; p < 2; p++) {
                int row = wc * 32 + p * 16 + lrow;
                u32 off = (u32)(row * LDS_H + col) * 2;
                ldsm_x4(bfr[p][0], bfr[p][1], bfr[p][2], bfr[p][3], sB + off);
            }
            u32 b0[2][2], b1[2][2];
#pragma unroll
            for (int p = 0; p < 2; p++) {
                b0[p][0] = bfr[p][0]; b0[p][1] = bfr[p][2];
                b1[p][0] = bfr[p][1]; b1[p][1] = bfr[p][3];
            }
            // hi pass (all 16 slots)
#pragma unroll
            for (int mt = 0; mt < 4; mt++)
#pragma unroll
                for (int p = 0; p < 2; p++) {
                    mma16816h(acc[mt][2 * p],     ahi[mt], b0[p]);
                    mma16816h(acc[mt][2 * p + 1], ahi[mt], b1[p]);
                }
            // lo pass (Q projection only)
            if (twoPass) {
#pragma unroll
                for (int mt = 0; mt < 4; mt++)
#pragma unroll
                    for (int p = 0; p < 2; p++) {
                        mma16816h(acc[mt][2 * p],     alo[mt], b0[p]);
                        mma16816h(acc[mt][2 * p + 1], alo[mt], b1[p]);
                    }
            }
        }
        __syncthreads();
    }

    // ---- epilogue: two 64-col half passes through smem
    float* sD = (float*)smem;   // [128][68] = 34816 B
    const int c2  = (tid & 31) * 2;
    const int rr0 = tid >> 5;   // 0..7

#pragma unroll
    for (int hc = 0; hc < 2; hc++) {
        __syncthreads();
        if ((wc >> 1) == hc) {
#pragma unroll
            for (int mt = 0; mt < 4; mt++)
#pragma unroll
                for (int nt = 0; nt < 4; nt++) {
                    int row = wr * 64 + mt * 16 + (lane >> 2);
                    int col = (wc & 1) * 32 + nt * 8 + (lane & 3) * 2;
                    sD[row * 68 + col + 0]       = acc[mt][nt][0];
                    sD[row * 68 + col + 1]       = acc[mt][nt][1];
                    sD[(row + 8) * 68 + col + 0] = acc[mt][nt][2];
                    sD[(row + 8) * 68 + col + 1] = acc[mt][nt][3];
                }
        }
        __syncthreads();

        if (!isOut) {
            const int h = blockIdx.x;      // BN == hd == 128
            const int d = hc * 64 + c2;
#pragma unroll 4
            for (int rr = 0; rr < 16; rr++) {
                int r = rr * 8 + rr0;
                int m = mBase + r;
                int b = m >> 11, t = m & (Tn - 1);
                size_t idx = (size_t)((b * Hn + h) * Tn + t) * HDn + d;
                float v0 = sD[r * 68 + c2];
                float v1 = sD[r * 68 + c2 + 1];
                if (mat == 0) {
                    float h0 = __half2float(__float2half(v0));
                    float h1 = __half2float(__float2half(v1));
                    *(u32*)&g_Qhi[idx] = pack_f16x2(v0, v1);
                    *(u32*)&g_Qlo[idx] = pack_f16x2(v0 - h0, v1 - h1);
                } else if (mat == 1) {
                    *(u32*)&g_Kh[idx] = pack_f16x2(v0, v1);
                } else {
                    *(u32*)&g_Vh[idx] = pack_f16x2(v0, v1);
                }
            }
        } else {
#pragma unroll 4
            for (int rr = 0; rr < 16; rr++) {
                int r = rr * 8 + rr0;
                int m = mBase + r;
                float2 v = make_float2(sD[r * 68 + c2], sD[r * 68 + c2 + 1]);
                *(float2*)&OutParam[(size_t)m * Cn + nBase + hc * 64 + c2] = v;
            }
        }
    }
}

// ---------------------------------------------------------------------------
// HMMA fused relu-attention (unchanged from R11).
// S = (Qhi + Qlo) * K : fp16 2-pass. W(fp16) @ V(fp16) single pass.
// Q fragments hoisted out of the kt loop.
// ---------------------------------------------------------------------------
constexpr int AT_STR  = 136;
constexpr int AT_Q_B  = 128 * AT_STR * 2;                 // 34816
constexpr int AT_KV_B = 64 * AT_STR * 2;                  // 17408
constexpr int ATTN_SMEM = 2 * AT_Q_B + 4 * AT_KV_B;       // 139264

__global__ __launch_bounds__(256, 1)
void attn_hmma()
{
    extern __shared__ char smem[];
    const u32 sQh = smem_to_u32(smem);
    const u32 sQl = sQh + AT_Q_B;
    const u32 sS0 = sQl + AT_Q_B;
    const u32 sS1 = sS0 + 2 * AT_KV_B;

    const int tid  = threadIdx.x;
    const int lane = tid & 31;
    const int w    = tid >> 5;

    const int qt  = (gridDim.x - 1) - blockIdx.x;
    const int bh  = blockIdx.y;
    const int qg0 = qt * 128;

    const __half* Qhg = g_Qhi + ((size_t)bh * Tn + qg0) * HDn;
    const __half* Qlg = g_Qlo + ((size_t)bh * Tn + qg0) * HDn;
    const __half* Kg  = g_Kh  + (size_t)bh * Tn * HDn;
    const __half* Vg  = g_Vh  + (size_t)bh * Tn * HDn;

    auto load_kv = [&](int kt, u32 st) {
        const int kr = tid >> 2, kseg = (tid & 3) * 32;
        const size_t gro = (size_t)(kt * 64 + kr) * HDn;
        const u32 so = (kr * AT_STR + kseg) * 2;
#pragma unroll
        for (int i = 0; i < 4; i++) {
            int c = i * 8;
            cp16(st + so + c * 2,            Kg + gro + kseg + c);
            cp16(st + AT_KV_B + so + c * 2,  Vg + gro + kseg + c);
        }
        CP_COMMIT();
    };

    // ---- prologue: Q hi/lo, then KV tile 0
    {
        const int r = tid >> 1, cseg = (tid & 1) * 64;
#pragma unroll
        for (int i = 0; i < 8; i++) {
            int col = cseg + i * 8;
            cp16(sQh + (r * AT_STR + col) * 2, Qhg + (size_t)r * HDn + col);
            cp16(sQl + (r * AT_STR + col) * 2, Qlg + (size_t)r * HDn + col);
        }
        CP_COMMIT();
    }
    load_kv(0, sS0);

    CP_WAIT(1);
    __syncthreads();

    u32 qh[8][4], ql[8][4];
    {
        const int row = w * 16 + (lane & 15);
#pragma unroll
        for (int c16 = 0; c16 < 8; c16++) {
            int col = c16 * 16 + (lane >> 4) * 8;
            u32 off = (u32)(row * AT_STR + col) * 2;
            ldsm_x4(qh[c16][0], qh[c16][1], qh[c16][2], qh[c16][3], sQh + off);
            ldsm_x4(ql[c16][0], ql[c16][1], ql[c16][2], ql[c16][3], sQl + off);
        }
    }

    const int ktmax = 2 * qt + 1;

    float o[16][4];
#pragma unroll
    for (int i = 0; i < 16; i++)
#pragma unroll
        for (int r = 0; r < 4; r++) o[i][r] = 0.f;
    float rs0 = 0.f, rs1 = 0.f;

    const int r0 = qg0 + w * 16 + (lane >> 2);
    const int r1 = r0 + 8;

    for (int kt = 0; kt <= ktmax; kt++) {
        if (kt + 1 <= ktmax) {
            load_kv(kt + 1, ((kt + 1) & 1) ? sS1 : sS0);
            CP_WAIT(1);
        } else {
            CP_WAIT(0);
        }
        __syncthreads();

        const u32 st = (kt & 1) ? sS1 : sS0;
        const u32 cK = st;
        const u32 cV = st + AT_KV_B;

        float s[8][4];
#pragma unroll
        for (int i = 0; i < 8; i++)
#pragma unroll
            for (int r = 0; r < 4; r++) s[i][r] = 0.f;

#pragma unroll
        for (int c16 = 0; c16 < 8; c16++) {
            u32 kb[4][4];
#pragma unroll
            for (int np = 0; np < 4; np++) {
                int row = np * 16 + (lane & 15);
                int col = c16 * 16 + (lane >> 4) * 8;
                u32 off = (u32)(row * AT_STR + col) * 2;
                ldsm_x4(kb[np][0], kb[np][1], kb[np][2], kb[np][3], cK + off);
            }
            u32 b2[8][2];
#pragma unroll
            for (int np = 0; np < 4; np++) {
                b2[2 * np][0]     = kb[np][0]; b2[2 * np][1]     = kb[np][2];
                b2[2 * np + 1][0] = kb[np][1]; b2[2 * np + 1][1] = kb[np][3];
            }
#pragma unroll
            for (int t = 0; t < 8; t++) mma16816h(s[t], qh[c16], b2[t]);
#pragma unroll
            for (int t = 0; t < 8; t++) mma16816h(s[t], ql[c16], b2[t]);
        }

        const bool diag = (kt >= 2 * qt);
        u32 wf[4][4];
#pragma unroll
        for (int n8 = 0; n8 < 8; n8++) {
            int kg = kt * 64 + n8 * 8 + (lane & 3) * 2;
            float e0 = fmaxf(fmaf(s[n8][0], SCALE, 0.1f), 0.f);
            float e1 = fmaxf(fmaf(s[n8][1], SCALE, 0.1f), 0.f);
            float e2 = fmaxf(fmaf(s[n8][2], SCALE, 0.1f), 0.f);
            float e3 = fmaxf(fmaf(s[n8][3], SCALE, 0.1f), 0.f);
            if (diag) {
                if (kg     > r0) e0 = 0.f;
                if (kg + 1 > r0) e1 = 0.f;
                if (kg     > r1) e2 = 0.f;
                if (kg + 1 > r1) e3 = 0.f;
            }
            rs0 += e0 + e1;
            rs1 += e2 + e3;
            s[n8][0] = e0; s[n8][1] = e1; s[n8][2] = e2; s[n8][3] = e3;
        }
#pragma unroll
        for (int t = 0; t < 4; t++) {
            wf[t][0] = pack_f16x2(s[2 * t][0],     s[2 * t][1]);
            wf[t][1] = pack_f16x2(s[2 * t][2],     s[2 * t][3]);
            wf[t][2] = pack_f16x2(s[2 * t + 1][0], s[2 * t + 1][1]);
            wf[t][3] = pack_f16x2(s[2 * t + 1][2], s[2 * t + 1][3]);
        }

#pragma unroll
        for (int t = 0; t < 4; t++) {
#pragma unroll
            for (int d2 = 0; d2 < 8; d2++) {
                u32 vb[4];
                int row = t * 16 + (lane & 15);
                int col = d2 * 16 + (lane >> 4) * 8;
                ldsm_x4_t(vb[0], vb[1], vb[2], vb[3], cV + (row * AT_STR + col) * 2);
                u32 b0[2] = { vb[0], vb[1] };
                u32 b1[2] = { vb[2], vb[3] };
                mma16816h(o[2 * d2],     wf[t], b0);
                mma16816h(o[2 * d2 + 1], wf[t], b1);
            }
        }
        __syncthreads();
    }

    rs0 += __shfl_xor_sync(0xffffffffu, rs0, 1);
    rs0 += __shfl_xor_sync(0xffffffffu, rs0, 2);
    rs1 += __shfl_xor_sync(0xffffffffu, rs1, 1);
    rs1 += __shfl_xor_sync(0xffffffffu, rs1, 2);
    const float inv0 = 1.f / (rs0 + EPSv);
    const float inv1 = 1.f / (rs1 + EPSv);

    const int b  = bh >> 4, hh = bh & 15;
    const size_t base0 = ((size_t)(b * Tn + r0) * Cn) + hh * 128;
    const size_t base1 = ((size_t)(b * Tn + r1) * Cn) + hh * 128;

#pragma unroll
    for (int d8 = 0; d8 < 16; d8++) {
        int col = d8 * 8 + (lane & 3) * 2;
        float v0 = o[d8][0] * inv0, v1 = o[d8][1] * inv0;
        float u0 = o[d8][2] * inv1, u1 = o[d8][3] * inv1;
        *(u32*)&g_Ah[base0 + col] = pack_f16x2(v0, v1);
        *(u32*)&g_Ah[base1 + col] = pack_f16x2(u0, u1);
    }
}

// ---------------------------------------------------------------------------

extern "C" void kernel_launch(void* const* d_in, const int* in_sizes, int n_in,
                              void* d_out, int out_size)
{
    const float* x  = (const float*)d_in[0];
    const float* Wq = (const float*)d_in[1];
    const float* Wk = (const float*)d_in[2];
    const float* Wv = (const float*)d_in[3];
    const float* Wo = (const float*)d_in[4];
    float* out = (float*)d_out;

    cudaFuncSetAttribute(gemm_f16,
                         cudaFuncAttributeMaxDynamicSharedMemorySize, GEMM_SMEM);
    cudaFuncSetAttribute(attn_hmma,
                         cudaFuncAttributeMaxDynamicSharedMemorySize, ATTN_SMEM);

    const int nW4 = (Cn * Cn) / 4;
    const int nX4 = (Bn * Tn * Cn) / 4;
    const int totalPrep = 4 * nW4 + nX4;
    prep_kernel<<<(totalPrep + 255) / 256, 256>>>(x, Wq, Wk, Wv, Wo);

    dim3 gQKV(Cn / 128, (Bn * Tn) / 128, 3);
    gemm_f16<<<gQKV, 256, GEMM_SMEM>>>(0, nullptr);

    dim3 gAttn(Tn / 128, Bn * Hn);
    attn_hmma<<<gAttn, 256, ATTN_SMEM>>>();

    dim3 gOut(Cn / 128, (Bn * Tn) / 128, 1);
    gemm_f16<<<gOut, 256, GEMM_SMEM>>>(1, out);
}

// round 13
// speedup vs baseline: 2.0878x; 1.1941x over previous
#include <cuda_runtime.h>
#include <cuda_bf16.h>
#include <cuda_fp16.h>

typedef unsigned int       u32;
typedef unsigned long long u64;

// Problem constants
constexpr int Bn  = 2;
constexpr int Tn  = 2048;
constexpr int Cn  = 2048;
constexpr int Hn  = 16;
constexpr int HDn = 128;
constexpr float SCALE = 0.088388347648318447f;   // 1/sqrt(128)
constexpr float EPSv  = 1e-6f;

// ---------------------------------------------------------------------------
// Device-global scratch (all activations fp16 single precision;
// score-path rounding is damped by the relu-weight normalization)
// ---------------------------------------------------------------------------
__device__ __half g_Qh [(size_t)Bn * Hn * Tn * HDn];  // [B,H,T,hd]
__device__ __half g_Kh [(size_t)Bn * Hn * Tn * HDn];
__device__ __half g_Vh [(size_t)Bn * Hn * Tn * HDn];

__device__ __half g_Xh [(size_t)Bn * Tn * Cn];
__device__ __half g_Wh[4][(size_t)Cn * Cn];
__device__ __half g_Ah [(size_t)Bn * Tn * Cn];        // attn out fp16

// ---------------------------------------------------------------------------
// PTX helpers
// ---------------------------------------------------------------------------
__device__ __forceinline__ u32 smem_to_u32(const void* p) {
    u32 a;
    asm("{ .reg .u64 t; cvta.to.shared.u64 t, %1; cvt.u32.u64 %0, t; }"
        : "=r"(a) : "l"(p));
    return a;
}

__device__ __forceinline__ void cp16(u32 saddr, const void* g) {
    asm volatile("cp.async.cg.shared.global [%0], [%1], 16;"
                 :: "r"(saddr), "l"(g) : "memory");
}
#define CP_COMMIT() asm volatile("cp.async.commit_group;" ::: "memory")
#define CP_WAIT(n)  asm volatile("cp.async.wait_group %0;" :: "n"(n) : "memory")

__device__ __forceinline__ void ldsm_x4(u32& r0, u32& r1, u32& r2, u32& r3, u32 addr) {
    asm volatile("ldmatrix.sync.aligned.m8n8.x4.shared.b16 {%0,%1,%2,%3}, [%4];"
                 : "=r"(r0), "=r"(r1), "=r"(r2), "=r"(r3) : "r"(addr));
}
__device__ __forceinline__ void ldsm_x4_t(u32& r0, u32& r1, u32& r2, u32& r3, u32 addr) {
    asm volatile("ldmatrix.sync.aligned.m8n8.x4.trans.shared.b16 {%0,%1,%2,%3}, [%4];"
                 : "=r"(r0), "=r"(r1), "=r"(r2), "=r"(r3) : "r"(addr));
}

__device__ __forceinline__ void mma16816h(float* d, const u32* a, const u32* b) {
    asm volatile(
        "mma.sync.aligned.m16n8k16.row.col.f32.f16.f16.f32 "
        "{%0,%1,%2,%3}, {%4,%5,%6,%7}, {%8,%9}, {%0,%1,%2,%3};"
        : "+f"(d[0]), "+f"(d[1]), "+f"(d[2]), "+f"(d[3])
        : "r"(a[0]), "r"(a[1]), "r"(a[2]), "r"(a[3]), "r"(b[0]), "r"(b[1]));
}

// pack {lo, hi} floats (lo -> bits[15:0])
__device__ __forceinline__ u32 pack_f16x2(float lo, float hi) {
    u32 r;
    asm("cvt.rn.f16x2.f32 %0, %1, %2;" : "=r"(r) : "f"(hi), "f"(lo));
    return r;
}

// ---------------------------------------------------------------------------
// Fused prologue: convert Wq/Wk/Wv/Wo and X to fp16 (single launch).
// ---------------------------------------------------------------------------
__global__ void prep_kernel(const float* __restrict__ x,
                            const float* __restrict__ Wq,
                            const float* __restrict__ Wk,
                            const float* __restrict__ Wv,
                            const float* __restrict__ Wo)
{
    const int nW4 = (Cn * Cn) / 4;
    const int nX4 = (Bn * Tn * Cn) / 4;
    const int total = 4 * nW4 + nX4;
    int g = blockIdx.x * blockDim.x + threadIdx.x;
    if (g >= total) return;

    const float* in;
    __half* dst;
    int i;
    if (g < 4 * nW4) {
        int which = g / nW4;
        i = (g - which * nW4) * 4;
        in = (which == 0) ? Wq : (which == 1) ? Wk : (which == 2) ? Wv : Wo;
        dst = g_Wh[which];
    } else {
        i = (g - 4 * nW4) * 4;
        in = x;
        dst = g_Xh;
    }
    float4 v = *(const float4*)(in + i);
    __half2* p = (__half2*)(dst + i);
    p[0] = __halves2half2(__float2half(v.x), __float2half(v.y));
    p[1] = __halves2half2(__float2half(v.z), __float2half(v.w));
}

// ---------------------------------------------------------------------------
// HMMA fp16 single-pass GEMM (R7 schedule): out[m,n] = sum_k A[m,k]*W[n,k]
// Block 128x128, BK=32, 8 warps (2x4), warp tile 64x32, double-buffered,
// 2 CTAs/SM.
// isOut==0: A=Xh, B=W[z]; out -> Qh (z=0), Kh (z=1), Vh (z=2), [B,H,T,hd]
// isOut==1: A=g_Ah, B=Wo; out -> fp32 OutParam
// ---------------------------------------------------------------------------
constexpr int GBK     = 32;
constexpr int LDS_H   = 40;
constexpr int TILE_B  = 128 * LDS_H * 2;          // 10240
constexpr int STAGE_B = 2 * TILE_B;               // 20480
constexpr int GEMM_SMEM = 2 * STAGE_B;            // 40960
constexpr int NCHUNK  = Cn / GBK;                 // 64

__global__ __launch_bounds__(256, 2)
void gemm_f16(int isOut, float* __restrict__ OutParam)
{
    extern __shared__ char smem[];
    const u32 sbase = smem_to_u32(smem);
    const int tid  = threadIdx.x;
    const int lane = tid & 31;
    const int warp = tid >> 5;
    const int wr   = warp >> 2;     // 0..1
    const int wc   = warp & 3;      // 0..3

    const int mat = isOut ? 3 : blockIdx.z;
    const __half* __restrict__ Am = isOut ? g_Ah : g_Xh;
    const __half* __restrict__ Bm = g_Wh[mat];

    const int mBase = blockIdx.y * 128;
    const int nBase = blockIdx.x * 128;

    float acc[4][4][4];
#pragma unroll
    for (int i = 0; i < 4; i++)
#pragma unroll
        for (int j = 0; j < 4; j++)
#pragma unroll
            for (int r = 0; r < 4; r++) acc[i][j][r] = 0.f;

    const int ldr = tid >> 1;
    const int ldc = (tid & 1) * 16;

    auto load_chunk = [&](int kc, int s) {
        const u32 sb = sbase + s * STAGE_B;
        const int k0 = kc * GBK;
        {
            const __half* g = Am + (size_t)(mBase + ldr) * Cn + k0 + ldc;
            u32 sa = sb + (ldr * LDS_H + ldc) * 2;
            cp16(sa,      g);
            cp16(sa + 16, g + 8);
        }
        {
            const __half* g = Bm + (size_t)(nBase + ldr) * Cn + k0 + ldc;
            u32 sa = sb + TILE_B + (ldr * LDS_H + ldc) * 2;
            cp16(sa,      g);
            cp16(sa + 16, g + 8);
        }
        CP_COMMIT();
    };

    load_chunk(0, 0);

    for (int c = 0; c < NCHUNK; c++) {
        const int s = c & 1;
        if (c + 1 < NCHUNK) load_chunk(c + 1, s ^ 1);
        if (c + 1 < NCHUNK) { CP_WAIT(1); } else { CP_WAIT(0); }
        __syncthreads();

        const u32 sb = sbase + s * STAGE_B;
        const u32 sA = sb;
        const u32 sB = sb + TILE_B;

#pragma unroll
        for (int k16 = 0; k16 < 2; k16++) {
            const int col = k16 * 16 + (lane >> 4) * 8;
            const int lrow = (lane & 15);

            u32 af[4][4], bfr[2][4];
#pragma unroll
            for (int mt = 0; mt < 4; mt++) {
                int row = wr * 64 + mt * 16 + lrow;
                u32 off = (u32)(row * LDS_H + col) * 2;
                ldsm_x4(af[mt][0], af[mt][1], af[mt][2], af[mt][3], sA + off);
            }
#pragma unroll
            for (int p = 0; p < 2; p++) {
                int row = wc * 32 + p * 16 + lrow;
                u32 off = (u32)(row * LDS_H + col) * 2;
                ldsm_x4(bfr[p][0], bfr[p][1], bfr[p][2], bfr[p][3], sB + off);
            }
            u32 b0[2][2], b1[2][2];
#pragma unroll
            for (int p = 0; p < 2; p++) {
                b0[p][0] = bfr[p][0]; b0[p][1] = bfr[p][2];
                b1[p][0] = bfr[p][1]; b1[p][1] = bfr[p][3];
            }
#pragma unroll
            for (int mt = 0; mt < 4; mt++)
#pragma unroll
                for (int p = 0; p < 2; p++) {
                    mma16816h(acc[mt][2 * p],     af[mt], b0[p]);
                    mma16816h(acc[mt][2 * p + 1], af[mt], b1[p]);
                }
        }
        __syncthreads();
    }

    // ---- epilogue: two 64-col half passes through smem
    float* sD = (float*)smem;   // [128][68] = 34816 B
    const int c2  = (tid & 31) * 2;
    const int rr0 = tid >> 5;   // 0..7

#pragma unroll
    for (int hc = 0; hc < 2; hc++) {
        __syncthreads();
        if ((wc >> 1) == hc) {
#pragma unroll
            for (int mt = 0; mt < 4; mt++)
#pragma unroll
                for (int nt = 0; nt < 4; nt++) {
                    int row = wr * 64 + mt * 16 + (lane >> 2);
                    int col = (wc & 1) * 32 + nt * 8 + (lane & 3) * 2;
                    sD[row * 68 + col + 0]       = acc[mt][nt][0];
                    sD[row * 68 + col + 1]       = acc[mt][nt][1];
                    sD[(row + 8) * 68 + col + 0] = acc[mt][nt][2];
                    sD[(row + 8) * 68 + col + 1] = acc[mt][nt][3];
                }
        }
        __syncthreads();

        if (!isOut) {
            __half* O = (mat == 0) ? g_Qh : (mat == 1) ? g_Kh : g_Vh;
            const int h = blockIdx.x;      // BN == hd == 128
            const int d = hc * 64 + c2;
#pragma unroll 4
            for (int rr = 0; rr < 16; rr++) {
                int r = rr * 8 + rr0;
                int m = mBase + r;
                int b = m >> 11, t = m & (Tn - 1);
                size_t idx = (size_t)((b * Hn + h) * Tn + t) * HDn + d;
                *(u32*)&O[idx] = pack_f16x2(sD[r * 68 + c2], sD[r * 68 + c2 + 1]);
            }
        } else {
#pragma unroll 4
            for (int rr = 0; rr < 16; rr++) {
                int r = rr * 8 + rr0;
                int m = mBase + r;
                float2 v = make_float2(sD[r * 68 + c2], sD[r * 68 + c2 + 1]);
                *(float2*)&OutParam[(size_t)m * Cn + nBase + hc * 64 + c2] = v;
            }
        }
    }
}

// ---------------------------------------------------------------------------
// HMMA fused relu-attention, all fp16 single pass.
// S = Q K^T; W(fp16) @ V(fp16). Q fragments hoisted out of the kt loop.
// Block: 128 q-rows x (b,h). 8 warps x 16 q-rows. 64-row K/V tiles, dbl-buf.
// ---------------------------------------------------------------------------
constexpr int AT_STR  = 136;
constexpr int AT_Q_B  = 128 * AT_STR * 2;                 // 34816
constexpr int AT_KV_B = 64 * AT_STR * 2;                  // 17408
constexpr int ATTN_SMEM = AT_Q_B + 4 * AT_KV_B;           // 104448

__global__ __launch_bounds__(256, 1)
void attn_hmma()
{
    extern __shared__ char smem[];
    const u32 sQ  = smem_to_u32(smem);
    const u32 sS0 = sQ + AT_Q_B;
    const u32 sS1 = sS0 + 2 * AT_KV_B;

    const int tid  = threadIdx.x;
    const int lane = tid & 31;
    const int w    = tid >> 5;

    const int qt  = (gridDim.x - 1) - blockIdx.x;
    const int bh  = blockIdx.y;
    const int qg0 = qt * 128;

    const __half* Qg = g_Qh + ((size_t)bh * Tn + qg0) * HDn;
    const __half* Kg = g_Kh + (size_t)bh * Tn * HDn;
    const __half* Vg = g_Vh + (size_t)bh * Tn * HDn;

    auto load_kv = [&](int kt, u32 st) {
        const int kr = tid >> 2, kseg = (tid & 3) * 32;
        const size_t gro = (size_t)(kt * 64 + kr) * HDn;
        const u32 so = (kr * AT_STR + kseg) * 2;
#pragma unroll
        for (int i = 0; i < 4; i++) {
            int c = i * 8;
            cp16(st + so + c * 2,            Kg + gro + kseg + c);
            cp16(st + AT_KV_B + so + c * 2,  Vg + gro + kseg + c);
        }
        CP_COMMIT();
    };

    // ---- prologue: Q, then KV tile 0
    {
        const int r = tid >> 1, cseg = (tid & 1) * 64;
#pragma unroll
        for (int i = 0; i < 8; i++) {
            int col = cseg + i * 8;
            cp16(sQ + (r * AT_STR + col) * 2, Qg + (size_t)r * HDn + col);
        }
        CP_COMMIT();
    }
    load_kv(0, sS0);

    CP_WAIT(1);
    __syncthreads();

    u32 qf[8][4];
    {
        const int row = w * 16 + (lane & 15);
#pragma unroll
        for (int c16 = 0; c16 < 8; c16++) {
            int col = c16 * 16 + (lane >> 4) * 8;
            u32 off = (u32)(row * AT_STR + col) * 2;
            ldsm_x4(qf[c16][0], qf[c16][1], qf[c16][2], qf[c16][3], sQ + off);
        }
    }

    const int ktmax = 2 * qt + 1;

    float o[16][4];
#pragma unroll
    for (int i = 0; i < 16; i++)
#pragma unroll
        for (int r = 0; r < 4; r++) o[i][r] = 0.f;
    float rs0 = 0.f, rs1 = 0.f;

    const int r0 = qg0 + w * 16 + (lane >> 2);
    const int r1 = r0 + 8;

    for (int kt = 0; kt <= ktmax; kt++) {
        if (kt + 1 <= ktmax) {
            load_kv(kt + 1, ((kt + 1) & 1) ? sS1 : sS0);
            CP_WAIT(1);
        } else {
            CP_WAIT(0);
        }
        __syncthreads();

        const u32 st = (kt & 1) ? sS1 : sS0;
        const u32 cK = st;
        const u32 cV = st + AT_KV_B;

        // ---- S = Q K^T (single fp16 pass), warp: 16 x 64
        float s[8][4];
#pragma unroll
        for (int i = 0; i < 8; i++)
#pragma unroll
            for (int r = 0; r < 4; r++) s[i][r] = 0.f;

#pragma unroll
        for (int c16 = 0; c16 < 8; c16++) {
            u32 kb[4][4];
#pragma unroll
            for (int np = 0; np < 4; np++) {
                int row = np * 16 + (lane & 15);
                int col = c16 * 16 + (lane >> 4) * 8;
                u32 off = (u32)(row * AT_STR + col) * 2;
                ldsm_x4(kb[np][0], kb[np][1], kb[np][2], kb[np][3], cK + off);
            }
            u32 b2[8][2];
#pragma unroll
            for (int np = 0; np < 4; np++) {
                b2[2 * np][0]     = kb[np][0]; b2[2 * np][1]     = kb[np][2];
                b2[2 * np + 1][0] = kb[np][1]; b2[2 * np + 1][1] = kb[np][3];
            }
#pragma unroll
            for (int t = 0; t < 8; t++) mma16816h(s[t], qf[c16], b2[t]);
        }

        // ---- relu + mask + rowsum; pack as fp16 A-frags
        const bool diag = (kt >= 2 * qt);
        u32 wf[4][4];
#pragma unroll
        for (int n8 = 0; n8 < 8; n8++) {
            int kg = kt * 64 + n8 * 8 + (lane & 3) * 2;
            float e0 = fmaxf(fmaf(s[n8][0], SCALE, 0.1f), 0.f);
            float e1 = fmaxf(fmaf(s[n8][1], SCALE, 0.1f), 0.f);
            float e2 = fmaxf(fmaf(s[n8][2], SCALE, 0.1f), 0.f);
            float e3 = fmaxf(fmaf(s[n8][3], SCALE, 0.1f), 0.f);
            if (diag) {
                if (kg     > r0) e0 = 0.f;
                if (kg + 1 > r0) e1 = 0.f;
                if (kg     > r1) e2 = 0.f;
                if (kg + 1 > r1) e3 = 0.f;
            }
            rs0 += e0 + e1;
            rs1 += e2 + e3;
            s[n8][0] = e0; s[n8][1] = e1; s[n8][2] = e2; s[n8][3] = e3;
        }
#pragma unroll
        for (int t = 0; t < 4; t++) {
            wf[t][0] = pack_f16x2(s[2 * t][0],     s[2 * t][1]);
            wf[t][1] = pack_f16x2(s[2 * t][2],     s[2 * t][3]);
            wf[t][2] = pack_f16x2(s[2 * t + 1][0], s[2 * t + 1][1]);
            wf[t][3] = pack_f16x2(s[2 * t + 1][2], s[2 * t + 1][3]);
        }

        // ---- O += W V (fp16, warp: 16 x 128, k = 64)
#pragma unroll
        for (int t = 0; t < 4; t++) {
#pragma unroll
            for (int d2 = 0; d2 < 8; d2++) {
                u32 vb[4];
                int row = t * 16 + (lane & 15);
                int col = d2 * 16 + (lane >> 4) * 8;
                ldsm_x4_t(vb[0], vb[1], vb[2], vb[3], cV + (row * AT_STR + col) * 2);
                u32 b0[2] = { vb[0], vb[1] };
                u32 b1[2] = { vb[2], vb[3] };
                mma16816h(o[2 * d2],     wf[t], b0);
                mma16816h(o[2 * d2 + 1], wf[t], b1);
            }
        }
        __syncthreads();
    }

    // ---- rowsum reduce, normalize, store fp16
    rs0 += __shfl_xor_sync(0xffffffffu, rs0, 1);
    rs0 += __shfl_xor_sync(0xffffffffu, rs0, 2);
    rs1 += __shfl_xor_sync(0xffffffffu, rs1, 1);
    rs1 += __shfl_xor_sync(0xffffffffu, rs1, 2);
    const float inv0 = 1.f / (rs0 + EPSv);
    const float inv1 = 1.f / (rs1 + EPSv);

    const int b  = bh >> 4, hh = bh & 15;
    const size_t base0 = ((size_t)(b * Tn + r0) * Cn) + hh * 128;
    const size_t base1 = ((size_t)(b * Tn + r1) * Cn) + hh * 128;

#pragma unroll
    for (int d8 = 0; d8 < 16; d8++) {
        int col = d8 * 8 + (lane & 3) * 2;
        float v0 = o[d8][0] * inv0, v1 = o[d8][1] * inv0;
        float u0 = o[d8][2] * inv1, u1 = o[d8][3] * inv1;
        *(u32*)&g_Ah[base0 + col] = pack_f16x2(v0, v1);
        *(u32*)&g_Ah[base1 + col] = pack_f16x2(u0, u1);
    }
}

// ---------------------------------------------------------------------------

extern "C" void kernel_launch(void* const* d_in, const int* in_sizes, int n_in,
                              void* d_out, int out_size)
{
    const float* x  = (const float*)d_in[0];
    const float* Wq = (const float*)d_in[1];
    const float* Wk = (const float*)d_in[2];
    const float* Wv = (const float*)d_in[3];
    const float* Wo = (const float*)d_in[4];
    float* out = (float*)d_out;

    cudaFuncSetAttribute(gemm_f16,
                         cudaFuncAttributeMaxDynamicSharedMemorySize, GEMM_SMEM);
    cudaFuncSetAttribute(attn_hmma,
                         cudaFuncAttributeMaxDynamicSharedMemorySize, ATTN_SMEM);

    const int nW4 = (Cn * Cn) / 4;
    const int nX4 = (Bn * Tn * Cn) / 4;
    const int totalPrep = 4 * nW4 + nX4;
    prep_kernel<<<(totalPrep + 255) / 256, 256>>>(x, Wq, Wk, Wv, Wo);

    dim3 gQKV(Cn / 128, (Bn * Tn) / 128, 3);
    gemm_f16<<<gQKV, 256, GEMM_SMEM>>>(0, nullptr);

    dim3 gAttn(Tn / 128, Bn * Hn);
    attn_hmma<<<gAttn, 256, ATTN_SMEM>>>();

    dim3 gOut(Cn / 128, (Bn * Tn) / 128, 1);
    gemm_f16<<<gOut, 256, GEMM_SMEM>>>(1, out);
}